// round 5
// baseline (speedup 1.0000x reference)
#include <cuda_runtime.h>
#include <math.h>

#define NN 100000
#define NE 1600000
#define IND 64
#define HID 128
#define NG 512

// ---------------- scratch (device globals: no allocation allowed) ----------------
__device__ int   g_deg_out[NN];
__device__ int   g_deg_in[NN];
__device__ int   g_off[NN + 1];
__device__ int   g_cursor[NN];
__device__ int   g_csr[NE];
__device__ float g_rsdo[NN];
__device__ float g_rsdi[NN];
__device__ float g_xs[(size_t)NN * IND];     // x * rsqrt(deg_out)
__device__ float g_agg[(size_t)NN * HID];    // aggregation output (stride 64 for L1, 128 for L2)
__device__ float g_h1s[(size_t)NN * HID];    // relu(L1)*rsqrt(deg_out)
__device__ float g_h2[(size_t)NN * HID];     // relu(L2)
__device__ float g_gsum[NG * HID];
__device__ int   g_gcnt[NG];

// ---------------- init / degree / scan / csr ----------------
__global__ void k_init() {
    int i = blockIdx.x * blockDim.x + threadIdx.x;
    int stride = gridDim.x * blockDim.x;
    for (int j = i; j < NN; j += stride) { g_deg_out[j] = 0; g_deg_in[j] = 0; g_cursor[j] = 0; }
    for (int j = i; j < NG * HID; j += stride) g_gsum[j] = 0.f;
    for (int j = i; j < NG; j += stride) g_gcnt[j] = 0;
}

__global__ void k_deg(const int* __restrict__ src, const int* __restrict__ dst) {
    int i = blockIdx.x * blockDim.x + threadIdx.x;
    int stride = gridDim.x * blockDim.x;
    for (int e = i; e < NE; e += stride) {
        atomicAdd(&g_deg_out[src[e]], 1);
        atomicAdd(&g_deg_in[dst[e]], 1);
    }
}

// single-block exclusive scan over deg_in -> g_off; also emits rsqrt(deg) tables.
// N = 100000, 1024 threads, ~98 elems/thread.
__global__ void k_scan() {
    __shared__ int ss[1024];
    const int t = threadIdx.x;
    const int C = (NN + 1023) / 1024;  // 98
    int start = t * C;
    int cnt = NN - start; if (cnt < 0) cnt = 0; if (cnt > C) cnt = C;
    int local = 0;
    for (int j = 0; j < cnt; j++) local += g_deg_in[start + j];
    ss[t] = local;
    __syncthreads();
    // Hillis-Steele inclusive scan
    for (int off = 1; off < 1024; off <<= 1) {
        int v = (t >= off) ? ss[t - off] : 0;
        __syncthreads();
        ss[t] += v;
        __syncthreads();
    }
    int run = ss[t] - local;  // exclusive prefix of this chunk
    for (int j = 0; j < cnt; j++) {
        int di = g_deg_in[start + j];
        g_off[start + j] = run;
        run += di;
        g_rsdi[start + j] = rsqrtf(fmaxf((float)di, 1.f));
        g_rsdo[start + j] = rsqrtf(fmaxf((float)g_deg_out[start + j], 1.f));
    }
    if (t == 1023) g_off[NN] = ss[1023];
}

__global__ void k_fill(const int* __restrict__ src, const int* __restrict__ dst) {
    int i = blockIdx.x * blockDim.x + threadIdx.x;
    int stride = gridDim.x * blockDim.x;
    for (int e = i; e < NE; e += stride) {
        int d = dst[e];
        int s = src[e];
        int base = __ldg(&g_off[d]);
        int p = atomicAdd(&g_cursor[d], 1);
        g_csr[base + p] = s;
    }
}

// xs = x * rsqrt(deg_out)   (vectorized: 16 float4 per node)
__global__ void k_scale(const float* __restrict__ x) {
    int i = blockIdx.x * blockDim.x + threadIdx.x;
    int stride = gridDim.x * blockDim.x;
    const float4* x4 = reinterpret_cast<const float4*>(x);
    float4* o4 = reinterpret_cast<float4*>(g_xs);
    for (int j = i; j < NN * 16; j += stride) {
        float s = g_rsdo[j >> 4];
        float4 v = x4[j];
        v.x *= s; v.y *= s; v.z *= s; v.w *= s;
        o4[j] = v;
    }
}

// ---------------- aggregation (warp per dst node, CSR pull) ----------------
__global__ void k_agg64() {  // g_xs (stride 64) -> g_agg (stride 64), scaled by rsdi
    int warp = (blockIdx.x * blockDim.x + threadIdx.x) >> 5;
    int lane = threadIdx.x & 31;
    if (warp >= NN) return;
    int beg = g_off[warp], end = g_off[warp + 1];
    float2 acc = make_float2(0.f, 0.f);
    const float* in = g_xs;
    for (int base = beg; base < end; base += 32) {
        int m = end - base; if (m > 32) m = 32;
        int idx = (lane < m) ? __ldg(&g_csr[base + lane]) : 0;
        int j = 0;
        for (; j + 2 <= m; j += 2) {
            int s0 = __shfl_sync(0xffffffffu, idx, j);
            int s1 = __shfl_sync(0xffffffffu, idx, j + 1);
            float2 v0 = *reinterpret_cast<const float2*>(in + (size_t)s0 * 64 + lane * 2);
            float2 v1 = *reinterpret_cast<const float2*>(in + (size_t)s1 * 64 + lane * 2);
            acc.x += v0.x + v1.x;
            acc.y += v0.y + v1.y;
        }
        if (j < m) {
            int s0 = __shfl_sync(0xffffffffu, idx, j);
            float2 v0 = *reinterpret_cast<const float2*>(in + (size_t)s0 * 64 + lane * 2);
            acc.x += v0.x; acc.y += v0.y;
        }
    }
    float r = g_rsdi[warp];
    acc.x *= r; acc.y *= r;
    *reinterpret_cast<float2*>(g_agg + (size_t)warp * 64 + lane * 2) = acc;
}

__global__ void k_agg128() {  // g_h1s (stride 128) -> g_agg (stride 128), scaled by rsdi
    int warp = (blockIdx.x * blockDim.x + threadIdx.x) >> 5;
    int lane = threadIdx.x & 31;
    if (warp >= NN) return;
    int beg = g_off[warp], end = g_off[warp + 1];
    float4 acc = make_float4(0.f, 0.f, 0.f, 0.f);
    const float* in = g_h1s;
    for (int base = beg; base < end; base += 32) {
        int m = end - base; if (m > 32) m = 32;
        int idx = (lane < m) ? __ldg(&g_csr[base + lane]) : 0;
        int j = 0;
        for (; j + 2 <= m; j += 2) {
            int s0 = __shfl_sync(0xffffffffu, idx, j);
            int s1 = __shfl_sync(0xffffffffu, idx, j + 1);
            float4 v0 = *reinterpret_cast<const float4*>(in + (size_t)s0 * 128 + lane * 4);
            float4 v1 = *reinterpret_cast<const float4*>(in + (size_t)s1 * 128 + lane * 4);
            acc.x += v0.x + v1.x; acc.y += v0.y + v1.y;
            acc.z += v0.z + v1.z; acc.w += v0.w + v1.w;
        }
        if (j < m) {
            int s0 = __shfl_sync(0xffffffffu, idx, j);
            float4 v0 = *reinterpret_cast<const float4*>(in + (size_t)s0 * 128 + lane * 4);
            acc.x += v0.x; acc.y += v0.y; acc.z += v0.z; acc.w += v0.w;
        }
    }
    float r = g_rsdi[warp];
    acc.x *= r; acc.y *= r; acc.z *= r; acc.w *= r;
    *reinterpret_cast<float4*>(g_agg + (size_t)warp * 128 + lane * 4) = acc;
}

// ---------------- GEMM: out[N,128] = relu(A[N,KDIM] @ W[KDIM,128] + b) (* scale) ---------
// block: 256 threads (32,8), tile 64 nodes x 128 features, k staged in chunks of 64.
template <int KDIM, bool SCALE>
__device__ __forceinline__ void gemm_body(const float* __restrict__ A,
                                          const float* __restrict__ W,
                                          const float* __restrict__ bias,
                                          const float* __restrict__ scale,
                                          float* __restrict__ out) {
    __shared__ float Ws[64 * 128];
    __shared__ float As[64 * 64];
    const int tx = threadIdx.x;        // 0..31 -> features tx*4..tx*4+3
    const int ty = threadIdx.y;        // 0..7  -> nodes ty + 8*i
    const int tid = ty * 32 + tx;
    const int row0 = blockIdx.x * 64;

    float4 acc[8];
#pragma unroll
    for (int i = 0; i < 8; i++) acc[i] = make_float4(0.f, 0.f, 0.f, 0.f);

    for (int k0 = 0; k0 < KDIM; k0 += 64) {
        const float4* Wg = reinterpret_cast<const float4*>(W + k0 * 128);
#pragma unroll
        for (int i = 0; i < 8; i++)
            reinterpret_cast<float4*>(Ws)[tid + i * 256] = Wg[tid + i * 256];
#pragma unroll
        for (int i = 0; i < 4; i++) {
            int li = tid + i * 256;
            int r = li >> 4, c = li & 15;
            int node = row0 + r;
            float4 v = make_float4(0.f, 0.f, 0.f, 0.f);
            if (node < NN)
                v = *reinterpret_cast<const float4*>(A + (size_t)node * KDIM + k0 + c * 4);
            reinterpret_cast<float4*>(As)[li] = v;
        }
        __syncthreads();
#pragma unroll 8
        for (int kk = 0; kk < 64; kk++) {
            float4 wf = *reinterpret_cast<const float4*>(Ws + kk * 128 + tx * 4);
#pragma unroll
            for (int i = 0; i < 8; i++) {
                float a = As[(ty + 8 * i) * 64 + kk];
                acc[i].x = fmaf(a, wf.x, acc[i].x);
                acc[i].y = fmaf(a, wf.y, acc[i].y);
                acc[i].z = fmaf(a, wf.z, acc[i].z);
                acc[i].w = fmaf(a, wf.w, acc[i].w);
            }
        }
        __syncthreads();
    }

    float4 bb = *reinterpret_cast<const float4*>(bias + tx * 4);
#pragma unroll
    for (int i = 0; i < 8; i++) {
        int node = row0 + ty + 8 * i;
        if (node < NN) {
            float4 v;
            v.x = fmaxf(acc[i].x + bb.x, 0.f);
            v.y = fmaxf(acc[i].y + bb.y, 0.f);
            v.z = fmaxf(acc[i].z + bb.z, 0.f);
            v.w = fmaxf(acc[i].w + bb.w, 0.f);
            if (SCALE) {
                float s = scale[node];
                v.x *= s; v.y *= s; v.z *= s; v.w *= s;
            }
            *reinterpret_cast<float4*>(out + (size_t)node * 128 + tx * 4) = v;
        }
    }
}

__global__ void __launch_bounds__(256) k_gemm1(const float* __restrict__ W, const float* __restrict__ b) {
    gemm_body<64, true>(g_agg, W, b, g_rsdo, g_h1s);
}
__global__ void __launch_bounds__(256) k_gemm2(const float* __restrict__ W, const float* __restrict__ b) {
    gemm_body<128, false>(g_agg, W, b, nullptr, g_h2);
}

// ---------------- mean-pool over sorted graph_ids (run-length + few atomics) ----------
// 128 nodes per block (shorter serial chain), 128 feature-threads.
#define POOL_CHUNK 128
__global__ void k_pool(const int* __restrict__ gid) {
    int t = threadIdx.x;           // feature 0..127
    int n0 = blockIdx.x * POOL_CHUNK;
    float acc = 0.f;
    int curg = -1, run = 0;
    for (int j = 0; j < POOL_CHUNK; j++) {
        int n = n0 + j;
        if (n >= NN) break;
        int g = __ldg(&gid[n]);
        if (g != curg) {
            if (curg >= 0) {
                atomicAdd(&g_gsum[curg * 128 + t], acc);
                if (t == 0) atomicAdd(&g_gcnt[curg], run);
            }
            acc = 0.f; run = 0; curg = g;
        }
        acc += g_h2[(size_t)n * 128 + t];
        run++;
    }
    if (curg >= 0) {
        atomicAdd(&g_gsum[curg * 128 + t], acc);
        if (t == 0) atomicAdd(&g_gcnt[curg], run);
    }
}

// ---------------- MLP head: 512 graphs, block per graph ----------------
__global__ void k_mlp(const float* __restrict__ Wc1, const float* __restrict__ bc1,
                      const float* __restrict__ Wc2, const float* __restrict__ bc2,
                      const float* __restrict__ Wc3, const float* __restrict__ bc3,
                      float* __restrict__ out) {
    __shared__ float h[128];
    __shared__ float o1[128];
    __shared__ float red[128];
    int g = blockIdx.x, t = threadIdx.x;
    float cnt = fmaxf((float)g_gcnt[g], 1.f);
    h[t] = g_gsum[g * 128 + t] / cnt;
    __syncthreads();
    float s = bc1[t];
#pragma unroll 8
    for (int k = 0; k < 128; k++) s = fmaf(h[k], __ldg(&Wc1[k * 128 + t]), s);
    o1[t] = fmaxf(s, 0.f);
    __syncthreads();
    float s2 = bc2[t];
#pragma unroll 8
    for (int k = 0; k < 128; k++) s2 = fmaf(o1[k], __ldg(&Wc2[k * 128 + t]), s2);
    float o2 = fmaxf(s2, 0.f);
    float p = o2 * __ldg(&Wc3[t]);
    red[t] = p;
    __syncthreads();
    if (t < 64) red[t] += red[t + 64];
    __syncthreads();
    if (t < 32) {
        float v = red[t] + red[t + 32];
#pragma unroll
        for (int o = 16; o > 0; o >>= 1) v += __shfl_down_sync(0xffffffffu, v, o);
        if (t == 0) out[g] = v + bc3[0];
    }
}

// ---------------- launch ----------------
extern "C" void kernel_launch(void* const* d_in, const int* in_sizes, int n_in,
                              void* d_out, int out_size) {
    (void)in_sizes; (void)n_in; (void)out_size;
    const float* x   = (const float*)d_in[0];
    const int*  esrc = (const int*)d_in[1];
    const int*  edst = (const int*)d_in[2];
    const int*  gid  = (const int*)d_in[3];
    const float* W1 = (const float*)d_in[4];
    const float* b1 = (const float*)d_in[5];
    const float* W2 = (const float*)d_in[6];
    const float* b2 = (const float*)d_in[7];
    const float* Wc1 = (const float*)d_in[8];
    const float* bc1 = (const float*)d_in[9];
    const float* Wc2 = (const float*)d_in[10];
    const float* bc2 = (const float*)d_in[11];
    const float* Wc3 = (const float*)d_in[12];
    const float* bc3 = (const float*)d_in[13];
    float* out = (float*)d_out;

    k_init<<<592, 256>>>();
    k_deg<<<1184, 256>>>(esrc, edst);
    k_scan<<<1, 1024>>>();           // also fills g_rsdi / g_rsdo
    k_fill<<<1184, 256>>>(esrc, edst);
    k_scale<<<1184, 256>>>(x);

    // layer 1: aggregate (64-d) then GEMM 64->128 with relu * rsqrt(deg_out)
    k_agg64<<<(NN + 7) / 8, 256>>>();
    k_gemm1<<<(NN + 63) / 64, dim3(32, 8)>>>(W1, b1);

    // layer 2: aggregate (128-d) then GEMM 128->128 with relu
    k_agg128<<<(NN + 7) / 8, 256>>>();
    k_gemm2<<<(NN + 63) / 64, dim3(32, 8)>>>(W2, b2);

    // mean-pool + MLP head
    k_pool<<<(NN + POOL_CHUNK - 1) / POOL_CHUNK, 128>>>(gid);
    k_mlp<<<NG, 128>>>(Wc1, bc1, Wc2, bc2, Wc3, bc3, out);
}

// round 8
// speedup vs baseline: 1.7830x; 1.7830x over previous
#include <cuda_runtime.h>
#include <math.h>

#define NN 100000
#define NE 1600000
#define IND 64
#define HID 128
#define NG 512
#define SCB 98   // scan blocks: 98*1024 = 100352 >= NN

// ---------------- scratch (device globals: no allocation allowed) ----------------
__device__ int   g_deg_out[NN];
__device__ int   g_deg_in[NN];
__device__ int   g_off[NN + 1];
__device__ int   g_cursor[NN];
__device__ int   g_csr[NE];
__device__ int   g_part[SCB];
__device__ int   g_partoff[SCB];
__device__ float g_rsdo[NN];
__device__ float g_rsdi[NN];
__device__ float g_xs[(size_t)NN * IND];     // x * rsqrt(deg_out)
__device__ float g_agg[(size_t)NN * HID];    // aggregation output
__device__ float g_h1s[(size_t)NN * HID];    // relu(L1)*rsqrt(deg_out)
__device__ float g_h2[(size_t)NN * HID];     // relu(L2)
__device__ float g_gsum[NG * HID];
__device__ int   g_gcnt[NG];

// ---------------- init / degree ----------------
__global__ void k_init() {
    int i = blockIdx.x * blockDim.x + threadIdx.x;
    int stride = gridDim.x * blockDim.x;
    for (int j = i; j < NN; j += stride) { g_deg_out[j] = 0; g_deg_in[j] = 0; g_cursor[j] = 0; }
    for (int j = i; j < NG * HID; j += stride) g_gsum[j] = 0.f;
    for (int j = i; j < NG; j += stride) g_gcnt[j] = 0;
}

__global__ void k_deg(const int* __restrict__ src, const int* __restrict__ dst) {
    int i = blockIdx.x * blockDim.x + threadIdx.x;
    int stride = gridDim.x * blockDim.x;
    for (int e = i; e < NE; e += stride) {
        atomicAdd(&g_deg_out[src[e]], 1);
        atomicAdd(&g_deg_in[dst[e]], 1);
    }
}

// ---------------- 3-phase coalesced scan ----------------
// phase 1: per-block sums of deg_in + rsqrt tables (fully coalesced)
__global__ void __launch_bounds__(1024) k_scan1() {
    __shared__ int red[1024];
    int t = threadIdx.x;
    int i = blockIdx.x * 1024 + t;
    int d = 0;
    if (i < NN) {
        d = g_deg_in[i];
        g_rsdi[i] = rsqrtf(fmaxf((float)d, 1.f));
        g_rsdo[i] = rsqrtf(fmaxf((float)g_deg_out[i], 1.f));
    }
    red[t] = d;
    __syncthreads();
    for (int off = 512; off > 0; off >>= 1) {
        if (t < off) red[t] += red[t + off];
        __syncthreads();
    }
    if (t == 0) g_part[blockIdx.x] = red[0];
}

// phase 2: exclusive scan of 98 partials (one tiny block)
__global__ void k_scan2() {
    __shared__ int ss[128];
    int t = threadIdx.x;
    int v = (t < SCB) ? g_part[t] : 0;
    ss[t] = v;
    __syncthreads();
    for (int off = 1; off < 128; off <<= 1) {
        int u = (t >= off) ? ss[t - off] : 0;
        __syncthreads();
        ss[t] += u;
        __syncthreads();
    }
    if (t < SCB) g_partoff[t] = ss[t] - v;   // exclusive
    if (t == 0) g_off[NN] = NE;              // total degree = NE by construction
}

// phase 3: per-block exclusive scan + apply block offset (coalesced)
__global__ void __launch_bounds__(1024) k_scan3() {
    __shared__ int ss[1024];
    int t = threadIdx.x;
    int i = blockIdx.x * 1024 + t;
    int d = (i < NN) ? g_deg_in[i] : 0;
    ss[t] = d;
    __syncthreads();
    for (int off = 1; off < 1024; off <<= 1) {
        int u = (t >= off) ? ss[t - off] : 0;
        __syncthreads();
        ss[t] += u;
        __syncthreads();
    }
    if (i < NN) g_off[i] = g_partoff[blockIdx.x] + ss[t] - d;  // exclusive prefix
}

__global__ void k_fill(const int* __restrict__ src, const int* __restrict__ dst) {
    int i = blockIdx.x * blockDim.x + threadIdx.x;
    int stride = gridDim.x * blockDim.x;
    for (int e = i; e < NE; e += stride) {
        int d = dst[e];
        int s = src[e];
        int base = __ldg(&g_off[d]);
        int p = atomicAdd(&g_cursor[d], 1);
        g_csr[base + p] = s;
    }
}

// xs = x * rsqrt(deg_out)
__global__ void k_scale(const float* __restrict__ x) {
    int i = blockIdx.x * blockDim.x + threadIdx.x;
    int stride = gridDim.x * blockDim.x;
    const float4* x4 = reinterpret_cast<const float4*>(x);
    float4* o4 = reinterpret_cast<float4*>(g_xs);
    for (int j = i; j < NN * 16; j += stride) {
        float s = g_rsdo[j >> 4];
        float4 v = x4[j];
        v.x *= s; v.y *= s; v.z *= s; v.w *= s;
        o4[j] = v;
    }
}

// ---------------- aggregation (warp per dst node, CSR pull, 4-deep ILP) ----------
__global__ void k_agg64() {
    int warp = (blockIdx.x * blockDim.x + threadIdx.x) >> 5;
    int lane = threadIdx.x & 31;
    if (warp >= NN) return;
    int beg = g_off[warp], end = g_off[warp + 1];
    float2 a0 = make_float2(0.f, 0.f), a1 = make_float2(0.f, 0.f);
    const float* in = g_xs;
    for (int base = beg; base < end; base += 32) {
        int m = end - base; if (m > 32) m = 32;
        int idx = (lane < m) ? __ldg(&g_csr[base + lane]) : 0;
        int j = 0;
        for (; j + 4 <= m; j += 4) {
            int s0 = __shfl_sync(0xffffffffu, idx, j);
            int s1 = __shfl_sync(0xffffffffu, idx, j + 1);
            int s2 = __shfl_sync(0xffffffffu, idx, j + 2);
            int s3 = __shfl_sync(0xffffffffu, idx, j + 3);
            float2 v0 = *reinterpret_cast<const float2*>(in + (size_t)s0 * 64 + lane * 2);
            float2 v1 = *reinterpret_cast<const float2*>(in + (size_t)s1 * 64 + lane * 2);
            float2 v2 = *reinterpret_cast<const float2*>(in + (size_t)s2 * 64 + lane * 2);
            float2 v3 = *reinterpret_cast<const float2*>(in + (size_t)s3 * 64 + lane * 2);
            a0.x += v0.x + v1.x; a0.y += v0.y + v1.y;
            a1.x += v2.x + v3.x; a1.y += v2.y + v3.y;
        }
        for (; j < m; j++) {
            int s0 = __shfl_sync(0xffffffffu, idx, j);
            float2 v0 = *reinterpret_cast<const float2*>(in + (size_t)s0 * 64 + lane * 2);
            a0.x += v0.x; a0.y += v0.y;
        }
    }
    float r = g_rsdi[warp];
    float2 acc; acc.x = (a0.x + a1.x) * r; acc.y = (a0.y + a1.y) * r;
    *reinterpret_cast<float2*>(g_agg + (size_t)warp * 64 + lane * 2) = acc;
}

__global__ void k_agg128() {
    int warp = (blockIdx.x * blockDim.x + threadIdx.x) >> 5;
    int lane = threadIdx.x & 31;
    if (warp >= NN) return;
    int beg = g_off[warp], end = g_off[warp + 1];
    float4 a0 = make_float4(0.f, 0.f, 0.f, 0.f), a1 = make_float4(0.f, 0.f, 0.f, 0.f);
    const float* in = g_h1s;
    for (int base = beg; base < end; base += 32) {
        int m = end - base; if (m > 32) m = 32;
        int idx = (lane < m) ? __ldg(&g_csr[base + lane]) : 0;
        int j = 0;
        for (; j + 4 <= m; j += 4) {
            int s0 = __shfl_sync(0xffffffffu, idx, j);
            int s1 = __shfl_sync(0xffffffffu, idx, j + 1);
            int s2 = __shfl_sync(0xffffffffu, idx, j + 2);
            int s3 = __shfl_sync(0xffffffffu, idx, j + 3);
            float4 v0 = *reinterpret_cast<const float4*>(in + (size_t)s0 * 128 + lane * 4);
            float4 v1 = *reinterpret_cast<const float4*>(in + (size_t)s1 * 128 + lane * 4);
            float4 v2 = *reinterpret_cast<const float4*>(in + (size_t)s2 * 128 + lane * 4);
            float4 v3 = *reinterpret_cast<const float4*>(in + (size_t)s3 * 128 + lane * 4);
            a0.x += v0.x + v1.x; a0.y += v0.y + v1.y; a0.z += v0.z + v1.z; a0.w += v0.w + v1.w;
            a1.x += v2.x + v3.x; a1.y += v2.y + v3.y; a1.z += v2.z + v3.z; a1.w += v2.w + v3.w;
        }
        for (; j < m; j++) {
            int s0 = __shfl_sync(0xffffffffu, idx, j);
            float4 v0 = *reinterpret_cast<const float4*>(in + (size_t)s0 * 128 + lane * 4);
            a0.x += v0.x; a0.y += v0.y; a0.z += v0.z; a0.w += v0.w;
        }
    }
    float r = g_rsdi[warp];
    float4 acc;
    acc.x = (a0.x + a1.x) * r; acc.y = (a0.y + a1.y) * r;
    acc.z = (a0.z + a1.z) * r; acc.w = (a0.w + a1.w) * r;
    *reinterpret_cast<float4*>(g_agg + (size_t)warp * 128 + lane * 4) = acc;
}

// ---------------- GEMM with packed f32x2 FMA (Blackwell FFMA2) ----------------
// out[N,128] = relu(A[N,KDIM] @ W[KDIM,128] + b) (* scale)
// block (32,8) = 256 thr, tile 64 nodes x 128 feats, K staged in 64-chunks.
// Each thread: 8 nodes x 4 feats; feats held as 2 packed f32x2 accumulators.
__device__ __forceinline__ unsigned long long pack2(float lo, float hi) {
    unsigned long long r;
    asm("mov.b64 %0, {%1, %2};" : "=l"(r) : "r"(__float_as_uint(lo)), "r"(__float_as_uint(hi)));
    return r;
}
__device__ __forceinline__ void unpack2(unsigned long long p, float& lo, float& hi) {
    unsigned int a, b;
    asm("mov.b64 {%0, %1}, %2;" : "=r"(a), "=r"(b) : "l"(p));
    lo = __uint_as_float(a); hi = __uint_as_float(b);
}
__device__ __forceinline__ void fma2(unsigned long long& acc, unsigned long long a, unsigned long long w) {
    asm("fma.rn.f32x2 %0, %1, %2, %0;" : "+l"(acc) : "l"(a), "l"(w));
}

template <int KDIM, bool SCALE>
__device__ __forceinline__ void gemm_body(const float* __restrict__ A,
                                          const float* __restrict__ W,
                                          const float* __restrict__ bias,
                                          const float* __restrict__ scale,
                                          float* __restrict__ out) {
    __shared__ float Ws[64 * 128];
    __shared__ float As[64 * 64];
    const int tx = threadIdx.x;        // 0..31 -> features tx*4..tx*4+3
    const int ty = threadIdx.y;        // 0..7  -> nodes ty + 8*i
    const int tid = ty * 32 + tx;
    const int row0 = blockIdx.x * 64;

    unsigned long long acc0[8], acc1[8];
#pragma unroll
    for (int i = 0; i < 8; i++) { acc0[i] = 0ull; acc1[i] = 0ull; }

    for (int k0 = 0; k0 < KDIM; k0 += 64) {
        const float4* Wg = reinterpret_cast<const float4*>(W + k0 * 128);
#pragma unroll
        for (int i = 0; i < 8; i++)
            reinterpret_cast<float4*>(Ws)[tid + i * 256] = Wg[tid + i * 256];
#pragma unroll
        for (int i = 0; i < 4; i++) {
            int li = tid + i * 256;
            int r = li >> 4, c = li & 15;
            int node = row0 + r;
            float4 v = make_float4(0.f, 0.f, 0.f, 0.f);
            if (node < NN)
                v = *reinterpret_cast<const float4*>(A + (size_t)node * KDIM + k0 + c * 4);
            reinterpret_cast<float4*>(As)[li] = v;
        }
        __syncthreads();
#pragma unroll 4
        for (int k4 = 0; k4 < 16; k4++) {
            float4 av[8];
#pragma unroll
            for (int i = 0; i < 8; i++)
                av[i] = *reinterpret_cast<const float4*>(As + (ty + 8 * i) * 64 + k4 * 4);
#pragma unroll
            for (int q = 0; q < 4; q++) {
                float4 wf = *reinterpret_cast<const float4*>(Ws + (k4 * 4 + q) * 128 + tx * 4);
                unsigned long long w0 = pack2(wf.x, wf.y);
                unsigned long long w1 = pack2(wf.z, wf.w);
#pragma unroll
                for (int i = 0; i < 8; i++) {
                    float a = (q == 0) ? av[i].x : (q == 1) ? av[i].y : (q == 2) ? av[i].z : av[i].w;
                    unsigned long long ap = pack2(a, a);
                    fma2(acc0[i], ap, w0);
                    fma2(acc1[i], ap, w1);
                }
            }
        }
        __syncthreads();
    }

    float4 bb = *reinterpret_cast<const float4*>(bias + tx * 4);
#pragma unroll
    for (int i = 0; i < 8; i++) {
        int node = row0 + ty + 8 * i;
        if (node < NN) {
            float4 v;
            unpack2(acc0[i], v.x, v.y);
            unpack2(acc1[i], v.z, v.w);
            v.x = fmaxf(v.x + bb.x, 0.f);
            v.y = fmaxf(v.y + bb.y, 0.f);
            v.z = fmaxf(v.z + bb.z, 0.f);
            v.w = fmaxf(v.w + bb.w, 0.f);
            if (SCALE) {
                float s = scale[node];
                v.x *= s; v.y *= s; v.z *= s; v.w *= s;
            }
            *reinterpret_cast<float4*>(out + (size_t)node * 128 + tx * 4) = v;
        }
    }
}

__global__ void __launch_bounds__(256) k_gemm1(const float* __restrict__ W, const float* __restrict__ b) {
    gemm_body<64, true>(g_agg, W, b, g_rsdo, g_h1s);
}
__global__ void __launch_bounds__(256) k_gemm2(const float* __restrict__ W, const float* __restrict__ b) {
    gemm_body<128, false>(g_agg, W, b, nullptr, g_h2);
}

// ---------------- mean-pool over sorted graph_ids ----------------
#define POOL_CHUNK 128
__global__ void k_pool(const int* __restrict__ gid) {
    int t = threadIdx.x;           // feature 0..127
    int n0 = blockIdx.x * POOL_CHUNK;
    float acc = 0.f;
    int curg = -1, run = 0;
    for (int j = 0; j < POOL_CHUNK; j++) {
        int n = n0 + j;
        if (n >= NN) break;
        int g = __ldg(&gid[n]);
        if (g != curg) {
            if (curg >= 0) {
                atomicAdd(&g_gsum[curg * 128 + t], acc);
                if (t == 0) atomicAdd(&g_gcnt[curg], run);
            }
            acc = 0.f; run = 0; curg = g;
        }
        acc += g_h2[(size_t)n * 128 + t];
        run++;
    }
    if (curg >= 0) {
        atomicAdd(&g_gsum[curg * 128 + t], acc);
        if (t == 0) atomicAdd(&g_gcnt[curg], run);
    }
}

// ---------------- MLP head ----------------
__global__ void k_mlp(const float* __restrict__ Wc1, const float* __restrict__ bc1,
                      const float* __restrict__ Wc2, const float* __restrict__ bc2,
                      const float* __restrict__ Wc3, const float* __restrict__ bc3,
                      float* __restrict__ out) {
    __shared__ float h[128];
    __shared__ float o1[128];
    __shared__ float red[128];
    int g = blockIdx.x, t = threadIdx.x;
    float cnt = fmaxf((float)g_gcnt[g], 1.f);
    h[t] = g_gsum[g * 128 + t] / cnt;
    __syncthreads();
    float s = bc1[t];
#pragma unroll 8
    for (int k = 0; k < 128; k++) s = fmaf(h[k], __ldg(&Wc1[k * 128 + t]), s);
    o1[t] = fmaxf(s, 0.f);
    __syncthreads();
    float s2 = bc2[t];
#pragma unroll 8
    for (int k = 0; k < 128; k++) s2 = fmaf(o1[k], __ldg(&Wc2[k * 128 + t]), s2);
    float o2 = fmaxf(s2, 0.f);
    float p = o2 * __ldg(&Wc3[t]);
    red[t] = p;
    __syncthreads();
    if (t < 64) red[t] += red[t + 64];
    __syncthreads();
    if (t < 32) {
        float v = red[t] + red[t + 32];
#pragma unroll
        for (int o = 16; o > 0; o >>= 1) v += __shfl_down_sync(0xffffffffu, v, o);
        if (t == 0) out[g] = v + bc3[0];
    }
}

// ---------------- launch ----------------
extern "C" void kernel_launch(void* const* d_in, const int* in_sizes, int n_in,
                              void* d_out, int out_size) {
    (void)in_sizes; (void)n_in; (void)out_size;
    const float* x   = (const float*)d_in[0];
    const int*  esrc = (const int*)d_in[1];
    const int*  edst = (const int*)d_in[2];
    const int*  gid  = (const int*)d_in[3];
    const float* W1 = (const float*)d_in[4];
    const float* b1 = (const float*)d_in[5];
    const float* W2 = (const float*)d_in[6];
    const float* b2 = (const float*)d_in[7];
    const float* Wc1 = (const float*)d_in[8];
    const float* bc1 = (const float*)d_in[9];
    const float* Wc2 = (const float*)d_in[10];
    const float* bc2 = (const float*)d_in[11];
    const float* Wc3 = (const float*)d_in[12];
    const float* bc3 = (const float*)d_in[13];
    float* out = (float*)d_out;

    k_init<<<592, 256>>>();
    k_deg<<<1184, 256>>>(esrc, edst);
    k_scan1<<<SCB, 1024>>>();
    k_scan2<<<1, 128>>>();
    k_scan3<<<SCB, 1024>>>();
    k_fill<<<1184, 256>>>(esrc, edst);
    k_scale<<<1184, 256>>>(x);

    // layer 1: aggregate (64-d) then GEMM 64->128 with relu * rsqrt(deg_out)
    k_agg64<<<(NN + 7) / 8, 256>>>();
    k_gemm1<<<(NN + 63) / 64, dim3(32, 8)>>>(W1, b1);

    // layer 2: aggregate (128-d) then GEMM 128->128 with relu
    k_agg128<<<(NN + 7) / 8, 256>>>();
    k_gemm2<<<(NN + 63) / 64, dim3(32, 8)>>>(W2, b2);

    // mean-pool + MLP head
    k_pool<<<(NN + POOL_CHUNK - 1) / POOL_CHUNK, 128>>>(gid);
    k_mlp<<<NG, 128>>>(Wc1, bc1, Wc2, bc2, Wc3, bc3, out);
}

// round 9
// speedup vs baseline: 1.9183x; 1.0759x over previous
#include <cuda_runtime.h>
#include <cuda_fp16.h>
#include <math.h>

#define NN 100000
#define NE 1600000
#define IND 64
#define HID 128
#define NG 512
#define SCB 98   // scan blocks: 98*1024 = 100352 >= NN

// ---------------- scratch (device globals: no allocation allowed) ----------------
__device__ int    g_deg_out[NN];
__device__ int    g_deg_in[NN];
__device__ int    g_off[NN + 1];
__device__ int    g_cursor[NN];
__device__ int    g_csr[NE];
__device__ int    g_part[SCB];
__device__ int    g_partoff[SCB];
__device__ float  g_rsdo[NN];
__device__ float  g_rsdi[NN];
__device__ __half g_xsh[(size_t)NN * IND];    // fp16: x * rsqrt(deg_out)
__device__ float  g_agg[(size_t)NN * HID];    // fp32 aggregation output
__device__ __half g_h1sh[(size_t)NN * HID];   // fp16: relu(L1)*rsqrt(deg_out)
__device__ float  g_h2[(size_t)NN * HID];     // fp32 relu(L2)
__device__ float  g_gsum[NG * HID];
__device__ int    g_gcnt[NG];

// ---------------- init / degree ----------------
__global__ void k_init() {
    int i = blockIdx.x * blockDim.x + threadIdx.x;
    int stride = gridDim.x * blockDim.x;
    for (int j = i; j < NN; j += stride) { g_deg_out[j] = 0; g_deg_in[j] = 0; g_cursor[j] = 0; }
    for (int j = i; j < NG * HID; j += stride) g_gsum[j] = 0.f;
    for (int j = i; j < NG; j += stride) g_gcnt[j] = 0;
}

__global__ void k_deg(const int* __restrict__ src, const int* __restrict__ dst) {
    int i = blockIdx.x * blockDim.x + threadIdx.x;
    int stride = gridDim.x * blockDim.x;
    for (int e = i; e < NE; e += stride) {
        atomicAdd(&g_deg_out[src[e]], 1);
        atomicAdd(&g_deg_in[dst[e]], 1);
    }
}

// ---------------- 3-phase coalesced scan ----------------
__global__ void __launch_bounds__(1024) k_scan1() {
    __shared__ int red[1024];
    int t = threadIdx.x;
    int i = blockIdx.x * 1024 + t;
    int d = 0;
    if (i < NN) {
        d = g_deg_in[i];
        g_rsdi[i] = rsqrtf(fmaxf((float)d, 1.f));
        g_rsdo[i] = rsqrtf(fmaxf((float)g_deg_out[i], 1.f));
    }
    red[t] = d;
    __syncthreads();
    for (int off = 512; off > 0; off >>= 1) {
        if (t < off) red[t] += red[t + off];
        __syncthreads();
    }
    if (t == 0) g_part[blockIdx.x] = red[0];
}

__global__ void k_scan2() {
    __shared__ int ss[128];
    int t = threadIdx.x;
    int v = (t < SCB) ? g_part[t] : 0;
    ss[t] = v;
    __syncthreads();
    for (int off = 1; off < 128; off <<= 1) {
        int u = (t >= off) ? ss[t - off] : 0;
        __syncthreads();
        ss[t] += u;
        __syncthreads();
    }
    if (t < SCB) g_partoff[t] = ss[t] - v;   // exclusive
    if (t == 0) g_off[NN] = NE;
}

__global__ void __launch_bounds__(1024) k_scan3() {
    __shared__ int ss[1024];
    int t = threadIdx.x;
    int i = blockIdx.x * 1024 + t;
    int d = (i < NN) ? g_deg_in[i] : 0;
    ss[t] = d;
    __syncthreads();
    for (int off = 1; off < 1024; off <<= 1) {
        int u = (t >= off) ? ss[t - off] : 0;
        __syncthreads();
        ss[t] += u;
        __syncthreads();
    }
    if (i < NN) g_off[i] = g_partoff[blockIdx.x] + ss[t] - d;
}

__global__ void k_fill(const int* __restrict__ src, const int* __restrict__ dst) {
    int i = blockIdx.x * blockDim.x + threadIdx.x;
    int stride = gridDim.x * blockDim.x;
    for (int e = i; e < NE; e += stride) {
        int d = dst[e];
        int s = src[e];
        int base = __ldg(&g_off[d]);
        int p = atomicAdd(&g_cursor[d], 1);
        g_csr[base + p] = s;
    }
}

// xs = fp16(x * rsqrt(deg_out)); one float4 -> one uint2 (4 halfs)
__global__ void k_scale(const float* __restrict__ x) {
    int i = blockIdx.x * blockDim.x + threadIdx.x;
    int stride = gridDim.x * blockDim.x;
    const float4* x4 = reinterpret_cast<const float4*>(x);
    uint2* o = reinterpret_cast<uint2*>(g_xsh);
    for (int j = i; j < NN * 16; j += stride) {
        float s = g_rsdo[j >> 4];
        float4 v = x4[j];
        __half2 p0 = __floats2half2_rn(v.x * s, v.y * s);
        __half2 p1 = __floats2half2_rn(v.z * s, v.w * s);
        uint2 u;
        u.x = *reinterpret_cast<unsigned*>(&p0);
        u.y = *reinterpret_cast<unsigned*>(&p1);
        o[j] = u;
    }
}

// ---------------- aggregation (warp per dst node, fp16 gather, fp32 accum) ----------
__global__ void k_agg64() {   // g_xsh (64 halfs/row) -> g_agg (stride 64 fp32)
    int warp = (blockIdx.x * blockDim.x + threadIdx.x) >> 5;
    int lane = threadIdx.x & 31;
    if (warp >= NN) return;
    int beg = g_off[warp], end = g_off[warp + 1];
    float2 a0 = make_float2(0.f, 0.f), a1 = make_float2(0.f, 0.f);
    const __half* in = g_xsh;
    for (int base = beg; base < end; base += 32) {
        int m = end - base; if (m > 32) m = 32;
        int idx = (lane < m) ? __ldg(&g_csr[base + lane]) : 0;
        int j = 0;
        for (; j + 4 <= m; j += 4) {
            int s0 = __shfl_sync(0xffffffffu, idx, j);
            int s1 = __shfl_sync(0xffffffffu, idx, j + 1);
            int s2 = __shfl_sync(0xffffffffu, idx, j + 2);
            int s3 = __shfl_sync(0xffffffffu, idx, j + 3);
            float2 v0 = __half22float2(*reinterpret_cast<const __half2*>(in + (size_t)s0 * 64 + lane * 2));
            float2 v1 = __half22float2(*reinterpret_cast<const __half2*>(in + (size_t)s1 * 64 + lane * 2));
            float2 v2 = __half22float2(*reinterpret_cast<const __half2*>(in + (size_t)s2 * 64 + lane * 2));
            float2 v3 = __half22float2(*reinterpret_cast<const __half2*>(in + (size_t)s3 * 64 + lane * 2));
            a0.x += v0.x + v1.x; a0.y += v0.y + v1.y;
            a1.x += v2.x + v3.x; a1.y += v2.y + v3.y;
        }
        for (; j < m; j++) {
            int s0 = __shfl_sync(0xffffffffu, idx, j);
            float2 v0 = __half22float2(*reinterpret_cast<const __half2*>(in + (size_t)s0 * 64 + lane * 2));
            a0.x += v0.x; a0.y += v0.y;
        }
    }
    float r = g_rsdi[warp];
    float2 acc; acc.x = (a0.x + a1.x) * r; acc.y = (a0.y + a1.y) * r;
    *reinterpret_cast<float2*>(g_agg + (size_t)warp * 64 + lane * 2) = acc;
}

__global__ void k_agg128() {  // g_h1sh (128 halfs/row) -> g_agg (stride 128 fp32)
    int warp = (blockIdx.x * blockDim.x + threadIdx.x) >> 5;
    int lane = threadIdx.x & 31;
    if (warp >= NN) return;
    int beg = g_off[warp], end = g_off[warp + 1];
    float4 a0 = make_float4(0.f, 0.f, 0.f, 0.f), a1 = make_float4(0.f, 0.f, 0.f, 0.f);
    const __half* in = g_h1sh;
    for (int base = beg; base < end; base += 32) {
        int m = end - base; if (m > 32) m = 32;
        int idx = (lane < m) ? __ldg(&g_csr[base + lane]) : 0;
        int j = 0;
        for (; j + 4 <= m; j += 4) {
            int s0 = __shfl_sync(0xffffffffu, idx, j);
            int s1 = __shfl_sync(0xffffffffu, idx, j + 1);
            int s2 = __shfl_sync(0xffffffffu, idx, j + 2);
            int s3 = __shfl_sync(0xffffffffu, idx, j + 3);
            uint2 r0 = *reinterpret_cast<const uint2*>(in + (size_t)s0 * 128 + lane * 4);
            uint2 r1 = *reinterpret_cast<const uint2*>(in + (size_t)s1 * 128 + lane * 4);
            uint2 r2 = *reinterpret_cast<const uint2*>(in + (size_t)s2 * 128 + lane * 4);
            uint2 r3 = *reinterpret_cast<const uint2*>(in + (size_t)s3 * 128 + lane * 4);
            float2 f0a = __half22float2(*reinterpret_cast<__half2*>(&r0.x));
            float2 f0b = __half22float2(*reinterpret_cast<__half2*>(&r0.y));
            float2 f1a = __half22float2(*reinterpret_cast<__half2*>(&r1.x));
            float2 f1b = __half22float2(*reinterpret_cast<__half2*>(&r1.y));
            float2 f2a = __half22float2(*reinterpret_cast<__half2*>(&r2.x));
            float2 f2b = __half22float2(*reinterpret_cast<__half2*>(&r2.y));
            float2 f3a = __half22float2(*reinterpret_cast<__half2*>(&r3.x));
            float2 f3b = __half22float2(*reinterpret_cast<__half2*>(&r3.y));
            a0.x += f0a.x + f1a.x; a0.y += f0a.y + f1a.y;
            a0.z += f0b.x + f1b.x; a0.w += f0b.y + f1b.y;
            a1.x += f2a.x + f3a.x; a1.y += f2a.y + f3a.y;
            a1.z += f2b.x + f3b.x; a1.w += f2b.y + f3b.y;
        }
        for (; j < m; j++) {
            int s0 = __shfl_sync(0xffffffffu, idx, j);
            uint2 r0 = *reinterpret_cast<const uint2*>(in + (size_t)s0 * 128 + lane * 4);
            float2 f0a = __half22float2(*reinterpret_cast<__half2*>(&r0.x));
            float2 f0b = __half22float2(*reinterpret_cast<__half2*>(&r0.y));
            a0.x += f0a.x; a0.y += f0a.y; a0.z += f0b.x; a0.w += f0b.y;
        }
    }
    float r = g_rsdi[warp];
    float4 acc;
    acc.x = (a0.x + a1.x) * r; acc.y = (a0.y + a1.y) * r;
    acc.z = (a0.z + a1.z) * r; acc.w = (a0.w + a1.w) * r;
    *reinterpret_cast<float4*>(g_agg + (size_t)warp * 128 + lane * 4) = acc;
}

// ---------------- GEMM with packed f32x2 FMA (Blackwell FFMA2) ----------------
__device__ __forceinline__ unsigned long long pack2(float lo, float hi) {
    unsigned long long r;
    asm("mov.b64 %0, {%1, %2};" : "=l"(r) : "r"(__float_as_uint(lo)), "r"(__float_as_uint(hi)));
    return r;
}
__device__ __forceinline__ void unpack2(unsigned long long p, float& lo, float& hi) {
    unsigned int a, b;
    asm("mov.b64 {%0, %1}, %2;" : "=r"(a), "=r"(b) : "l"(p));
    lo = __uint_as_float(a); hi = __uint_as_float(b);
}
__device__ __forceinline__ void fma2(unsigned long long& acc, unsigned long long a, unsigned long long w) {
    asm("fma.rn.f32x2 %0, %1, %2, %0;" : "+l"(acc) : "l"(a), "l"(w));
}

// OUTH: write fp16 (h1s path) vs fp32 (h2 path)
template <int KDIM, bool SCALE, bool OUTH>
__device__ __forceinline__ void gemm_body(const float* __restrict__ A,
                                          const float* __restrict__ W,
                                          const float* __restrict__ bias,
                                          const float* __restrict__ scale,
                                          float* __restrict__ outf,
                                          __half* __restrict__ outh) {
    __shared__ float Ws[64 * 128];
    __shared__ float As[64 * 64];
    const int tx = threadIdx.x;        // 0..31 -> features tx*4..tx*4+3
    const int ty = threadIdx.y;        // 0..7  -> nodes ty + 8*i
    const int tid = ty * 32 + tx;
    const int row0 = blockIdx.x * 64;

    unsigned long long acc0[8], acc1[8];
#pragma unroll
    for (int i = 0; i < 8; i++) { acc0[i] = 0ull; acc1[i] = 0ull; }

    for (int k0 = 0; k0 < KDIM; k0 += 64) {
        const float4* Wg = reinterpret_cast<const float4*>(W + k0 * 128);
#pragma unroll
        for (int i = 0; i < 8; i++)
            reinterpret_cast<float4*>(Ws)[tid + i * 256] = Wg[tid + i * 256];
#pragma unroll
        for (int i = 0; i < 4; i++) {
            int li = tid + i * 256;
            int r = li >> 4, c = li & 15;
            int node = row0 + r;
            float4 v = make_float4(0.f, 0.f, 0.f, 0.f);
            if (node < NN)
                v = *reinterpret_cast<const float4*>(A + (size_t)node * KDIM + k0 + c * 4);
            reinterpret_cast<float4*>(As)[li] = v;
        }
        __syncthreads();
#pragma unroll 4
        for (int k4 = 0; k4 < 16; k4++) {
            float4 av[8];
#pragma unroll
            for (int i = 0; i < 8; i++)
                av[i] = *reinterpret_cast<const float4*>(As + (ty + 8 * i) * 64 + k4 * 4);
#pragma unroll
            for (int q = 0; q < 4; q++) {
                float4 wf = *reinterpret_cast<const float4*>(Ws + (k4 * 4 + q) * 128 + tx * 4);
                unsigned long long w0 = pack2(wf.x, wf.y);
                unsigned long long w1 = pack2(wf.z, wf.w);
#pragma unroll
                for (int i = 0; i < 8; i++) {
                    float a = (q == 0) ? av[i].x : (q == 1) ? av[i].y : (q == 2) ? av[i].z : av[i].w;
                    unsigned long long ap = pack2(a, a);
                    fma2(acc0[i], ap, w0);
                    fma2(acc1[i], ap, w1);
                }
            }
        }
        __syncthreads();
    }

    float4 bb = *reinterpret_cast<const float4*>(bias + tx * 4);
#pragma unroll
    for (int i = 0; i < 8; i++) {
        int node = row0 + ty + 8 * i;
        if (node < NN) {
            float4 v;
            unpack2(acc0[i], v.x, v.y);
            unpack2(acc1[i], v.z, v.w);
            v.x = fmaxf(v.x + bb.x, 0.f);
            v.y = fmaxf(v.y + bb.y, 0.f);
            v.z = fmaxf(v.z + bb.z, 0.f);
            v.w = fmaxf(v.w + bb.w, 0.f);
            if (SCALE) {
                float s = scale[node];
                v.x *= s; v.y *= s; v.z *= s; v.w *= s;
            }
            if (OUTH) {
                __half2 p0 = __floats2half2_rn(v.x, v.y);
                __half2 p1 = __floats2half2_rn(v.z, v.w);
                uint2 u;
                u.x = *reinterpret_cast<unsigned*>(&p0);
                u.y = *reinterpret_cast<unsigned*>(&p1);
                reinterpret_cast<uint2*>(outh + (size_t)node * 128)[tx] = u;
            } else {
                *reinterpret_cast<float4*>(outf + (size_t)node * 128 + tx * 4) = v;
            }
        }
    }
}

__global__ void __launch_bounds__(256) k_gemm1(const float* __restrict__ W, const float* __restrict__ b) {
    gemm_body<64, true, true>(g_agg, W, b, g_rsdo, nullptr, g_h1sh);
}
__global__ void __launch_bounds__(256) k_gemm2(const float* __restrict__ W, const float* __restrict__ b) {
    gemm_body<128, false, false>(g_agg, W, b, nullptr, g_h2, nullptr);
}

// ---------------- mean-pool over sorted graph_ids ----------------
#define POOL_CHUNK 128
__global__ void k_pool(const int* __restrict__ gid) {
    int t = threadIdx.x;           // feature 0..127
    int n0 = blockIdx.x * POOL_CHUNK;
    float acc = 0.f;
    int curg = -1, run = 0;
    for (int j = 0; j < POOL_CHUNK; j++) {
        int n = n0 + j;
        if (n >= NN) break;
        int g = __ldg(&gid[n]);
        if (g != curg) {
            if (curg >= 0) {
                atomicAdd(&g_gsum[curg * 128 + t], acc);
                if (t == 0) atomicAdd(&g_gcnt[curg], run);
            }
            acc = 0.f; run = 0; curg = g;
        }
        acc += g_h2[(size_t)n * 128 + t];
        run++;
    }
    if (curg >= 0) {
        atomicAdd(&g_gsum[curg * 128 + t], acc);
        if (t == 0) atomicAdd(&g_gcnt[curg], run);
    }
}

// ---------------- MLP head ----------------
__global__ void k_mlp(const float* __restrict__ Wc1, const float* __restrict__ bc1,
                      const float* __restrict__ Wc2, const float* __restrict__ bc2,
                      const float* __restrict__ Wc3, const float* __restrict__ bc3,
                      float* __restrict__ out) {
    __shared__ float h[128];
    __shared__ float o1[128];
    __shared__ float red[128];
    int g = blockIdx.x, t = threadIdx.x;
    float cnt = fmaxf((float)g_gcnt[g], 1.f);
    h[t] = g_gsum[g * 128 + t] / cnt;
    __syncthreads();
    float s = bc1[t];
#pragma unroll 8
    for (int k = 0; k < 128; k++) s = fmaf(h[k], __ldg(&Wc1[k * 128 + t]), s);
    o1[t] = fmaxf(s, 0.f);
    __syncthreads();
    float s2 = bc2[t];
#pragma unroll 8
    for (int k = 0; k < 128; k++) s2 = fmaf(o1[k], __ldg(&Wc2[k * 128 + t]), s2);
    float o2 = fmaxf(s2, 0.f);
    float p = o2 * __ldg(&Wc3[t]);
    red[t] = p;
    __syncthreads();
    if (t < 64) red[t] += red[t + 64];
    __syncthreads();
    if (t < 32) {
        float v = red[t] + red[t + 32];
#pragma unroll
        for (int o = 16; o > 0; o >>= 1) v += __shfl_down_sync(0xffffffffu, v, o);
        if (t == 0) out[g] = v + bc3[0];
    }
}

// ---------------- launch ----------------
extern "C" void kernel_launch(void* const* d_in, const int* in_sizes, int n_in,
                              void* d_out, int out_size) {
    (void)in_sizes; (void)n_in; (void)out_size;
    const float* x   = (const float*)d_in[0];
    const int*  esrc = (const int*)d_in[1];
    const int*  edst = (const int*)d_in[2];
    const int*  gid  = (const int*)d_in[3];
    const float* W1 = (const float*)d_in[4];
    const float* b1 = (const float*)d_in[5];
    const float* W2 = (const float*)d_in[6];
    const float* b2 = (const float*)d_in[7];
    const float* Wc1 = (const float*)d_in[8];
    const float* bc1 = (const float*)d_in[9];
    const float* Wc2 = (const float*)d_in[10];
    const float* bc2 = (const float*)d_in[11];
    const float* Wc3 = (const float*)d_in[12];
    const float* bc3 = (const float*)d_in[13];
    float* out = (float*)d_out;

    k_init<<<592, 256>>>();
    k_deg<<<1184, 256>>>(esrc, edst);
    k_scan1<<<SCB, 1024>>>();
    k_scan2<<<1, 128>>>();
    k_scan3<<<SCB, 1024>>>();
    k_fill<<<1184, 256>>>(esrc, edst);
    k_scale<<<1184, 256>>>(x);

    // layer 1: aggregate (64-d fp16 gather) then GEMM 64->128, out fp16*rsdo
    k_agg64<<<(NN + 7) / 8, 256>>>();
    k_gemm1<<<(NN + 63) / 64, dim3(32, 8)>>>(W1, b1);

    // layer 2: aggregate (128-d fp16 gather) then GEMM 128->128, out fp32
    k_agg128<<<(NN + 7) / 8, 256>>>();
    k_gemm2<<<(NN + 63) / 64, dim3(32, 8)>>>(W2, b2);

    // mean-pool + MLP head
    k_pool<<<(NN + POOL_CHUNK - 1) / POOL_CHUNK, 128>>>(gid);
    k_mlp<<<NG, 128>>>(Wc1, bc1, Wc2, bc2, Wc3, bc3, out);
}

// round 15
// speedup vs baseline: 1.9414x; 1.0120x over previous
#include <cuda_runtime.h>
#include <cuda_fp16.h>
#include <mma.h>
#include <math.h>

using namespace nvcuda;

#define NN 100000
#define NE 1600000
#define IND 64
#define HID 128
#define NG 512
#define SCB 98   // scan blocks: 98*1024 = 100352 >= NN

// ---------------- scratch (device globals: no allocation allowed) ----------------
__device__ int    g_deg_out[NN];
__device__ int    g_deg_in[NN];
__device__ int    g_off[NN + 1];
__device__ int    g_cursor[NN];
__device__ int    g_csr[NE];
__device__ int    g_part[SCB];
__device__ int    g_partoff[SCB];
__device__ float  g_rsdo[NN];
__device__ float  g_rsdi[NN];
__device__ __half g_xsh[(size_t)NN * IND];    // fp16: x * rsqrt(deg_out)
__device__ __half g_aggh[(size_t)NN * HID];   // fp16 aggregation output (stride 64 L1, 128 L2)
__device__ __half g_h1sh[(size_t)NN * HID];   // fp16: relu(L1)*rsqrt(deg_out)
__device__ float  g_h2[(size_t)NN * HID];     // fp32 relu(L2)
__device__ __half g_w1h[IND * HID];           // fp16 W1
__device__ __half g_w2h[HID * HID];           // fp16 W2
__device__ float  g_gsum[NG * HID];
__device__ int    g_gcnt[NG];

// ---------------- init / degree ----------------
__global__ void k_init() {
    int i = blockIdx.x * blockDim.x + threadIdx.x;
    int stride = gridDim.x * blockDim.x;
    for (int j = i; j < NN; j += stride) { g_deg_out[j] = 0; g_deg_in[j] = 0; g_cursor[j] = 0; }
    for (int j = i; j < NG * HID; j += stride) g_gsum[j] = 0.f;
    for (int j = i; j < NG; j += stride) g_gcnt[j] = 0;
}

__global__ void k_deg(const int* __restrict__ src, const int* __restrict__ dst) {
    int i = blockIdx.x * blockDim.x + threadIdx.x;
    int stride = gridDim.x * blockDim.x;
    for (int e = i; e < NE; e += stride) {
        atomicAdd(&g_deg_out[src[e]], 1);
        atomicAdd(&g_deg_in[dst[e]], 1);
    }
}

// ---------------- 3-phase coalesced scan ----------------
__global__ void __launch_bounds__(1024) k_scan1() {
    __shared__ int red[1024];
    int t = threadIdx.x;
    int i = blockIdx.x * 1024 + t;
    int d = 0;
    if (i < NN) {
        d = g_deg_in[i];
        g_rsdi[i] = rsqrtf(fmaxf((float)d, 1.f));
        g_rsdo[i] = rsqrtf(fmaxf((float)g_deg_out[i], 1.f));
    }
    red[t] = d;
    __syncthreads();
    for (int off = 512; off > 0; off >>= 1) {
        if (t < off) red[t] += red[t + off];
        __syncthreads();
    }
    if (t == 0) g_part[blockIdx.x] = red[0];
}

__global__ void k_scan2() {
    __shared__ int ss[128];
    int t = threadIdx.x;
    int v = (t < SCB) ? g_part[t] : 0;
    ss[t] = v;
    __syncthreads();
    for (int off = 1; off < 128; off <<= 1) {
        int u = (t >= off) ? ss[t - off] : 0;
        __syncthreads();
        ss[t] += u;
        __syncthreads();
    }
    if (t < SCB) g_partoff[t] = ss[t] - v;   // exclusive
    if (t == 0) g_off[NN] = NE;
}

__global__ void __launch_bounds__(1024) k_scan3() {
    __shared__ int ss[1024];
    int t = threadIdx.x;
    int i = blockIdx.x * 1024 + t;
    int d = (i < NN) ? g_deg_in[i] : 0;
    ss[t] = d;
    __syncthreads();
    for (int off = 1; off < 1024; off <<= 1) {
        int u = (t >= off) ? ss[t - off] : 0;
        __syncthreads();
        ss[t] += u;
        __syncthreads();
    }
    if (i < NN) g_off[i] = g_partoff[blockIdx.x] + ss[t] - d;
}

__global__ void k_fill(const int* __restrict__ src, const int* __restrict__ dst) {
    int i = blockIdx.x * blockDim.x + threadIdx.x;
    int stride = gridDim.x * blockDim.x;
    for (int e = i; e < NE; e += stride) {
        int d = dst[e];
        int s = src[e];
        int base = __ldg(&g_off[d]);
        int p = atomicAdd(&g_cursor[d], 1);
        g_csr[base + p] = s;
    }
}

// convert weights to fp16 once
__global__ void k_convw(const float* __restrict__ W1, const float* __restrict__ W2) {
    int i = blockIdx.x * blockDim.x + threadIdx.x;
    int stride = gridDim.x * blockDim.x;
    for (int j = i; j < IND * HID + HID * HID; j += stride) {
        if (j < IND * HID) g_w1h[j] = __float2half(W1[j]);
        else               g_w2h[j - IND * HID] = __float2half(W2[j - IND * HID]);
    }
}

// xs = fp16(x * rsqrt(deg_out)); one float4 -> one uint2 (4 halfs)
__global__ void k_scale(const float* __restrict__ x) {
    int i = blockIdx.x * blockDim.x + threadIdx.x;
    int stride = gridDim.x * blockDim.x;
    const float4* x4 = reinterpret_cast<const float4*>(x);
    uint2* o = reinterpret_cast<uint2*>(g_xsh);
    for (int j = i; j < NN * 16; j += stride) {
        float s = g_rsdo[j >> 4];
        float4 v = x4[j];
        __half2 p0 = __floats2half2_rn(v.x * s, v.y * s);
        __half2 p1 = __floats2half2_rn(v.z * s, v.w * s);
        uint2 u;
        u.x = *reinterpret_cast<unsigned*>(&p0);
        u.y = *reinterpret_cast<unsigned*>(&p1);
        o[j] = u;
    }
}

// ---------------- aggregation (warp per dst node, fp16 gather, fp32 accum, fp16 out) --
__global__ void k_agg64() {
    int warp = (blockIdx.x * blockDim.x + threadIdx.x) >> 5;
    int lane = threadIdx.x & 31;
    if (warp >= NN) return;
    int beg = g_off[warp], end = g_off[warp + 1];
    float2 a0 = make_float2(0.f, 0.f), a1 = make_float2(0.f, 0.f);
    const __half* in = g_xsh;
    for (int base = beg; base < end; base += 32) {
        int m = end - base; if (m > 32) m = 32;
        int idx = (lane < m) ? __ldg(&g_csr[base + lane]) : 0;
        int j = 0;
        for (; j + 4 <= m; j += 4) {
            int s0 = __shfl_sync(0xffffffffu, idx, j);
            int s1 = __shfl_sync(0xffffffffu, idx, j + 1);
            int s2 = __shfl_sync(0xffffffffu, idx, j + 2);
            int s3 = __shfl_sync(0xffffffffu, idx, j + 3);
            float2 v0 = __half22float2(*reinterpret_cast<const __half2*>(in + (size_t)s0 * 64 + lane * 2));
            float2 v1 = __half22float2(*reinterpret_cast<const __half2*>(in + (size_t)s1 * 64 + lane * 2));
            float2 v2 = __half22float2(*reinterpret_cast<const __half2*>(in + (size_t)s2 * 64 + lane * 2));
            float2 v3 = __half22float2(*reinterpret_cast<const __half2*>(in + (size_t)s3 * 64 + lane * 2));
            a0.x += v0.x + v1.x; a0.y += v0.y + v1.y;
            a1.x += v2.x + v3.x; a1.y += v2.y + v3.y;
        }
        for (; j < m; j++) {
            int s0 = __shfl_sync(0xffffffffu, idx, j);
            float2 v0 = __half22float2(*reinterpret_cast<const __half2*>(in + (size_t)s0 * 64 + lane * 2));
            a0.x += v0.x; a0.y += v0.y;
        }
    }
    float r = g_rsdi[warp];
    __half2 h = __floats2half2_rn((a0.x + a1.x) * r, (a0.y + a1.y) * r);
    *reinterpret_cast<__half2*>(g_aggh + (size_t)warp * 64 + lane * 2) = h;
}

__global__ void k_agg128() {
    int warp = (blockIdx.x * blockDim.x + threadIdx.x) >> 5;
    int lane = threadIdx.x & 31;
    if (warp >= NN) return;
    int beg = g_off[warp], end = g_off[warp + 1];
    float4 a0 = make_float4(0.f, 0.f, 0.f, 0.f), a1 = make_float4(0.f, 0.f, 0.f, 0.f);
    const __half* in = g_h1sh;
    for (int base = beg; base < end; base += 32) {
        int m = end - base; if (m > 32) m = 32;
        int idx = (lane < m) ? __ldg(&g_csr[base + lane]) : 0;
        int j = 0;
        for (; j + 4 <= m; j += 4) {
            int s0 = __shfl_sync(0xffffffffu, idx, j);
            int s1 = __shfl_sync(0xffffffffu, idx, j + 1);
            int s2 = __shfl_sync(0xffffffffu, idx, j + 2);
            int s3 = __shfl_sync(0xffffffffu, idx, j + 3);
            uint2 r0 = *reinterpret_cast<const uint2*>(in + (size_t)s0 * 128 + lane * 4);
            uint2 r1 = *reinterpret_cast<const uint2*>(in + (size_t)s1 * 128 + lane * 4);
            uint2 r2 = *reinterpret_cast<const uint2*>(in + (size_t)s2 * 128 + lane * 4);
            uint2 r3 = *reinterpret_cast<const uint2*>(in + (size_t)s3 * 128 + lane * 4);
            float2 f0a = __half22float2(*reinterpret_cast<__half2*>(&r0.x));
            float2 f0b = __half22float2(*reinterpret_cast<__half2*>(&r0.y));
            float2 f1a = __half22float2(*reinterpret_cast<__half2*>(&r1.x));
            float2 f1b = __half22float2(*reinterpret_cast<__half2*>(&r1.y));
            float2 f2a = __half22float2(*reinterpret_cast<__half2*>(&r2.x));
            float2 f2b = __half22float2(*reinterpret_cast<__half2*>(&r2.y));
            float2 f3a = __half22float2(*reinterpret_cast<__half2*>(&r3.x));
            float2 f3b = __half22float2(*reinterpret_cast<__half2*>(&r3.y));
            a0.x += f0a.x + f1a.x; a0.y += f0a.y + f1a.y;
            a0.z += f0b.x + f1b.x; a0.w += f0b.y + f1b.y;
            a1.x += f2a.x + f3a.x; a1.y += f2a.y + f3a.y;
            a1.z += f2b.x + f3b.x; a1.w += f2b.y + f3b.y;
        }
        for (; j < m; j++) {
            int s0 = __shfl_sync(0xffffffffu, idx, j);
            uint2 r0 = *reinterpret_cast<const uint2*>(in + (size_t)s0 * 128 + lane * 4);
            float2 f0a = __half22float2(*reinterpret_cast<__half2*>(&r0.x));
            float2 f0b = __half22float2(*reinterpret_cast<__half2*>(&r0.y));
            a0.x += f0a.x; a0.y += f0a.y; a0.z += f0b.x; a0.w += f0b.y;
        }
    }
    float r = g_rsdi[warp];
    __half2 h0 = __floats2half2_rn((a0.x + a1.x) * r, (a0.y + a1.y) * r);
    __half2 h1 = __floats2half2_rn((a0.z + a1.z) * r, (a0.w + a1.w) * r);
    uint2 u;
    u.x = *reinterpret_cast<unsigned*>(&h0);
    u.y = *reinterpret_cast<unsigned*>(&h1);
    *reinterpret_cast<uint2*>(g_aggh + (size_t)warp * 128 + lane * 4) = u;
}

// ---------------- GEMM: fp16 wmma (m16n16k16), fp32 accumulate ----------------
// out[N,128] = relu(A[N,KDIM] @ W[KDIM,128] + b) (* scale)
// Block: 256 thr = 8 warps. Tile: 64 nodes x 128 feats. Warp w owns col tile n0=w*16,
// 4 row tiles of 16. A staged in smem fp16; B frags from L1-resident fp16 W.
template <int KDIM, bool SCALE, bool OUTH>
__device__ __forceinline__ void gemm_wmma_body(const __half* __restrict__ A,
                                               const __half* __restrict__ Wh,
                                               const float* __restrict__ bias,
                                               const float* __restrict__ scale,
                                               float* __restrict__ outf,
                                               __half* __restrict__ outh) {
    __shared__ __half Ash[64 * KDIM];
    __shared__ float Cs[8 * 256];
    const int tid = threadIdx.x;
    const int w = tid >> 5, lane = tid & 31;
    const int row0 = blockIdx.x * 64;

    // stage A tile (uint2 = 4 halfs), zero-pad rows past NN
    constexpr int RV = KDIM / 4;           // uint2 per row
    const uint2* Ag = reinterpret_cast<const uint2*>(A);
    uint2* As4 = reinterpret_cast<uint2*>(Ash);
#pragma unroll
    for (int i = tid; i < 64 * RV; i += 256) {
        int r = i / RV;
        int node = row0 + r;
        uint2 v = make_uint2(0u, 0u);
        if (node < NN) v = Ag[(size_t)node * RV + (i % RV)];
        As4[i] = v;
    }
    __syncthreads();

    const int n0 = w * 16;
    wmma::fragment<wmma::accumulator, 16, 16, 16, float> acc[4];
#pragma unroll
    for (int r = 0; r < 4; r++) wmma::fill_fragment(acc[r], 0.f);

#pragma unroll
    for (int kk = 0; kk < KDIM / 16; kk++) {
        wmma::fragment<wmma::matrix_b, 16, 16, 16, __half, wmma::row_major> bf;
        wmma::load_matrix_sync(bf, Wh + kk * 16 * HID + n0, HID);
#pragma unroll
        for (int r = 0; r < 4; r++) {
            wmma::fragment<wmma::matrix_a, 16, 16, 16, __half, wmma::row_major> af;
            wmma::load_matrix_sync(af, Ash + (r * 16) * KDIM + kk * 16, KDIM);
            wmma::mma_sync(acc[r], af, bf, acc[r]);
        }
    }

    // epilogue: per warp, tile -> smem -> bias/relu/scale -> vectorized store
    const int erow = lane >> 1;            // 0..15
    const int c8 = (lane & 1) * 8;         // 0 or 8
    float bb[8];
#pragma unroll
    for (int e = 0; e < 8; e++) bb[e] = bias[n0 + c8 + e];
    float* cs = Cs + w * 256;
#pragma unroll
    for (int r = 0; r < 4; r++) {
        wmma::store_matrix_sync(cs, acc[r], 16, wmma::mem_row_major);
        __syncwarp();
        int node = row0 + r * 16 + erow;
        if (node < NN) {
            float s = SCALE ? scale[node] : 1.f;
            float v[8];
#pragma unroll
            for (int e = 0; e < 8; e++) {
                float t = fmaxf(cs[erow * 16 + c8 + e] + bb[e], 0.f);
                v[e] = SCALE ? t * s : t;
            }
            if (OUTH) {
                __half2 h0 = __floats2half2_rn(v[0], v[1]);
                __half2 h1 = __floats2half2_rn(v[2], v[3]);
                __half2 h2 = __floats2half2_rn(v[4], v[5]);
                __half2 h3 = __floats2half2_rn(v[6], v[7]);
                uint4 u;
                u.x = *reinterpret_cast<unsigned*>(&h0);
                u.y = *reinterpret_cast<unsigned*>(&h1);
                u.z = *reinterpret_cast<unsigned*>(&h2);
                u.w = *reinterpret_cast<unsigned*>(&h3);
                *reinterpret_cast<uint4*>(outh + (size_t)node * HID + n0 + c8) = u;
            } else {
                float4 f0 = make_float4(v[0], v[1], v[2], v[3]);
                float4 f1 = make_float4(v[4], v[5], v[6], v[7]);
                float* o = outf + (size_t)node * HID + n0 + c8;
                *reinterpret_cast<float4*>(o) = f0;
                *reinterpret_cast<float4*>(o + 4) = f1;
            }
        }
        __syncwarp();   // protect Cs reuse
    }
}

__global__ void __launch_bounds__(256) k_gemm1(const float* __restrict__ b) {
    gemm_wmma_body<64, true, true>(g_aggh, g_w1h, b, g_rsdo, nullptr, g_h1sh);
}
__global__ void __launch_bounds__(256) k_gemm2(const float* __restrict__ b) {
    gemm_wmma_body<128, false, false>(g_aggh, g_w2h, b, nullptr, g_h2, nullptr);
}

// ---------------- mean-pool over sorted graph_ids ----------------
#define POOL_CHUNK 128
__global__ void k_pool(const int* __restrict__ gid) {
    int t = threadIdx.x;           // feature 0..127
    int n0 = blockIdx.x * POOL_CHUNK;
    float acc = 0.f;
    int curg = -1, run = 0;
    for (int j = 0; j < POOL_CHUNK; j++) {
        int n = n0 + j;
        if (n >= NN) break;
        int g = __ldg(&gid[n]);
        if (g != curg) {
            if (curg >= 0) {
                atomicAdd(&g_gsum[curg * 128 + t], acc);
                if (t == 0) atomicAdd(&g_gcnt[curg], run);
            }
            acc = 0.f; run = 0; curg = g;
        }
        acc += g_h2[(size_t)n * 128 + t];
        run++;
    }
    if (curg >= 0) {
        atomicAdd(&g_gsum[curg * 128 + t], acc);
        if (t == 0) atomicAdd(&g_gcnt[curg], run);
    }
}

// ---------------- MLP head ----------------
__global__ void k_mlp(const float* __restrict__ Wc1, const float* __restrict__ bc1,
                      const float* __restrict__ Wc2, const float* __restrict__ bc2,
                      const float* __restrict__ Wc3, const float* __restrict__ bc3,
                      float* __restrict__ out) {
    __shared__ float h[128];
    __shared__ float o1[128];
    __shared__ float red[128];
    int g = blockIdx.x, t = threadIdx.x;
    float cnt = fmaxf((float)g_gcnt[g], 1.f);
    h[t] = g_gsum[g * 128 + t] / cnt;
    __syncthreads();
    float s = bc1[t];
#pragma unroll 8
    for (int k = 0; k < 128; k++) s = fmaf(h[k], __ldg(&Wc1[k * 128 + t]), s);
    o1[t] = fmaxf(s, 0.f);
    __syncthreads();
    float s2 = bc2[t];
#pragma unroll 8
    for (int k = 0; k < 128; k++) s2 = fmaf(o1[k], __ldg(&Wc2[k * 128 + t]), s2);
    float o2 = fmaxf(s2, 0.f);
    float p = o2 * __ldg(&Wc3[t]);
    red[t] = p;
    __syncthreads();
    if (t < 64) red[t] += red[t + 64];
    __syncthreads();
    if (t < 32) {
        float v = red[t] + red[t + 32];
#pragma unroll
        for (int o = 16; o > 0; o >>= 1) v += __shfl_down_sync(0xffffffffu, v, o);
        if (t == 0) out[g] = v + bc3[0];
    }
}

// ---------------- launch ----------------
extern "C" void kernel_launch(void* const* d_in, const int* in_sizes, int n_in,
                              void* d_out, int out_size) {
    (void)in_sizes; (void)n_in; (void)out_size;
    const float* x   = (const float*)d_in[0];
    const int*  esrc = (const int*)d_in[1];
    const int*  edst = (const int*)d_in[2];
    const int*  gid  = (const int*)d_in[3];
    const float* W1 = (const float*)d_in[4];
    const float* b1 = (const float*)d_in[5];
    const float* W2 = (const float*)d_in[6];
    const float* b2 = (const float*)d_in[7];
    const float* Wc1 = (const float*)d_in[8];
    const float* bc1 = (const float*)d_in[9];
    const float* Wc2 = (const float*)d_in[10];
    const float* bc2 = (const float*)d_in[11];
    const float* Wc3 = (const float*)d_in[12];
    const float* bc3 = (const float*)d_in[13];
    float* out = (float*)d_out;

    k_init<<<592, 256>>>();
    k_deg<<<1184, 256>>>(esrc, edst);
    k_scan1<<<SCB, 1024>>>();
    k_scan2<<<1, 128>>>();
    k_scan3<<<SCB, 1024>>>();
    k_fill<<<1184, 256>>>(esrc, edst);
    k_scale<<<1184, 256>>>(x);
    k_convw<<<96, 256>>>(W1, W2);

    // layer 1: aggregate (64-d fp16) then wmma GEMM 64->128, out fp16*rsdo
    k_agg64<<<(NN + 7) / 8, 256>>>();
    k_gemm1<<<(NN + 63) / 64, 256>>>(b1);

    // layer 2: aggregate (128-d fp16) then wmma GEMM 128->128, out fp32
    k_agg128<<<(NN + 7) / 8, 256>>>();
    k_gemm2<<<(NN + 63) / 64, 256>>>(b2);

    // mean-pool + MLP head
    k_pool<<<(NN + POOL_CHUNK - 1) / POOL_CHUNK, 128>>>(gid);
    k_mlp<<<NG, 128>>>(Wc1, bc1, Wc2, bc2, Wc3, bc3, out);
}